// round 8
// baseline (speedup 1.0000x reference)
#include <cuda_runtime.h>
#include <cuda_fp16.h>
#include <cstdint>
#include <math.h>

#define NN   4096
#define FFD  2048
#define KTOT 4096   // concat K: [h0 (2048) | behavior (2048)]

// ---------------- device scratch (no cudaMalloc allowed) -------------------
static __device__ __half g_A[(size_t)NN * KTOT];              // 33.5MB  A fp16
static __device__ __half g_W[(size_t)4 * FFD * KTOT];         // 67MB    W^T fp16 [g*FFD+n][k]

// ---------------- helpers ---------------------------------------------------
__device__ __forceinline__ uint32_t smem_u32(const void* p) {
    uint32_t a;
    asm("{ .reg .u64 t; cvta.to.shared.u64 t, %1; cvt.u32.u64 %0, t; }"
        : "=r"(a) : "l"(p));
    return a;
}
__device__ __forceinline__ void cpa16(uint32_t s, const void* g) {
    asm volatile("cp.async.cg.shared.global [%0], [%1], 16;" :: "r"(s), "l"(g));
}
#define CPA_COMMIT() asm volatile("cp.async.commit_group;" ::: "memory")
#define CPA_WAIT3()  asm volatile("cp.async.wait_group 3;" ::: "memory")

__device__ __forceinline__ void ldsm4(uint32_t* r, uint32_t addr) {
    asm volatile("ldmatrix.sync.aligned.m8n8.x4.shared.b16 {%0,%1,%2,%3}, [%4];"
                 : "=r"(r[0]), "=r"(r[1]), "=r"(r[2]), "=r"(r[3]) : "r"(addr));
}
__device__ __forceinline__ void mma16816(float* c, const uint32_t* a, const uint32_t* b) {
    asm volatile("mma.sync.aligned.m16n8k16.row.col.f32.f16.f16.f32 "
                 "{%0,%1,%2,%3}, {%4,%5,%6,%7}, {%8,%9}, {%0,%1,%2,%3};"
                 : "+f"(c[0]), "+f"(c[1]), "+f"(c[2]), "+f"(c[3])
                 : "r"(a[0]), "r"(a[1]), "r"(a[2]), "r"(a[3]),
                   "r"(b[0]), "r"(b[1]));
}

// ---------------- pre-pass 1: A = [h0 | behavior] -> fp16 -------------------
__global__ __launch_bounds__(256)
void conv_A_kernel(const float* __restrict__ h0, const float* __restrict__ beh) {
    size_t e = ((size_t)blockIdx.x * 256 + threadIdx.x) * 4;
    int m = (int)(e >> 12);
    int k = (int)(e & 4095);
    const float* src = (k < 2048) ? (h0 + (size_t)m * 2048 + k)
                                  : (beh + (size_t)m * 2048 + (k - 2048));
    float4 v = *(const float4*)src;
    __half2* dh = (__half2*)(g_A + e);
    dh[0] = __halves2half2(__float2half_rn(v.x), __float2half_rn(v.y));
    dh[1] = __halves2half2(__float2half_rn(v.z), __float2half_rn(v.w));
}

// ---------------- pre-pass 2: W transpose -> fp16 [g*FFD+n][k] --------------
// src: [K=2048][N=2048] fp32 row-major. dst: g_W[(g*FFD+n)*KTOT + isx*2048 + k].
// 32x32 tile; convert to half in smem; packed 8B stores along k.
__global__ __launch_bounds__(256)
void conv_W_kernel(const float* Wi_h, const float* Wi_x,
                   const float* Wf_h, const float* Wf_x,
                   const float* Wg_h, const float* Wg_x,
                   const float* Wo_h, const float* Wo_x) {
    const float* srcs[8] = {Wi_h, Wi_x, Wf_h, Wf_x, Wg_h, Wg_x, Wo_h, Wo_x};
    int z = blockIdx.z;
    int g = z >> 1, isx = z & 1;
    const float* __restrict__ src = srcs[z];

    __shared__ __half t[32][33];   // [k_local][n_local], padded
    int k0 = blockIdx.x * 32, n0 = blockIdx.y * 32;
    int tid = threadIdx.x;

    // phase 1: coalesced fp32 reads (n contiguous), convert, store half to smem
    {
        int n_l = tid & 31;
        int k_l = tid >> 5;            // 0..7
#pragma unroll
        for (int i = 0; i < 4; i++) {
            int kk = k_l + i * 8;
            t[kk][n_l] = __float2half_rn(src[(size_t)(k0 + kk) * 2048 + n0 + n_l]);
        }
    }
    __syncthreads();

    // phase 2: each thread packs 4 consecutive k for one n -> 8B store
    {
        int n_l = tid >> 3;            // 0..31
        int k_q = (tid & 7) * 4;       // 0,4,...,28
        __half2 p0 = __halves2half2(t[k_q + 0][n_l], t[k_q + 1][n_l]);
        __half2 p1 = __halves2half2(t[k_q + 2][n_l], t[k_q + 3][n_l]);
        size_t o = ((size_t)g * FFD + n0 + n_l) * KTOT + isx * 2048 + k0 + k_q;
        __half2* dst = (__half2*)(g_W + o);
        dst[0] = p0;
        dst[1] = p1;
    }
}

// ---------------- fused 4-gate GEMM + LSTM epilogue -------------------------
// BM=128, BN=64 per gate (x4 gates), BK=64, 4 stages, 512 threads.
// 16 warps: warp_m in {0..3} (32 rows), warp_n in {0..3} (16 cols).
static constexpr int A_OFF    = 0;        // 128 rows x 128B = 16KB
static constexpr int WP_OFF   = 16384;    // 4 gates x 64 rows x 128B = 32KB
static constexpr int STAGE_SZ = 49152;    // 48KB
static constexpr int SMEM_TOTAL = 4 * STAGE_SZ;  // 192KB

__device__ __forceinline__ void fill_stage(uint32_t sb, int m0, int n0, int kb, int tid) {
#pragma unroll
    for (int i = 0; i < 2; i++) {               // A: 1024 16B units
        int u = tid + i * 512;
        int row = u >> 3, cu = u & 7;
        uint32_t sw = (uint32_t)(row * 128 + ((cu ^ (row & 7)) << 4));
        size_t go = (size_t)(m0 + row) * KTOT + kb + cu * 8;
        cpa16(sb + A_OFF + sw, g_A + go);
    }
#pragma unroll
    for (int i = 0; i < 4; i++) {               // W: 2048 16B units (4 gates x 64 rows)
        int u = tid + i * 512;
        int row = u >> 3, cu = u & 7;           // row 0..255: gate = row>>6, n = row&63
        uint32_t sw = (uint32_t)(row * 128 + ((cu ^ (row & 7)) << 4));
        size_t go = ((size_t)(row >> 6) * FFD + n0 + (row & 63)) * KTOT + kb + cu * 8;
        cpa16(sb + WP_OFF + sw, g_W + go);
    }
}

__global__ __launch_bounds__(512, 1)
void lstm_gemm_kernel(const float* __restrict__ c0, float* __restrict__ hout,
                      const float* __restrict__ bi, const float* __restrict__ bf,
                      const float* __restrict__ bg, const float* __restrict__ bo)
{
    extern __shared__ __align__(1024) char smem[];
    const uint32_t base = smem_u32(smem);
    const int tid = threadIdx.x;
    const int wid = tid >> 5;
    const int lane = tid & 31;
    const int warp_m = wid & 3;    // 4 warps over M (32 rows each)
    const int warp_n = wid >> 2;   // 4 warps over N (16 cols each)
    const int m0 = blockIdx.y * 128;
    const int n0 = blockIdx.x * 64;

    const int quad = lane >> 3, rr = lane & 7;
    const int rowA0 = warp_m * 32 + (quad & 1) * 8 + rr;      // + mi*16
    const int rowA1 = rowA0 + 16;
    const int chA = quad >> 1;
    const int rowB  = warp_n * 16 + (quad >> 1) * 8 + rr;     // within 64-row gate slab
    const int chB = quad & 1;
    const int rA7 = rowA0 & 7;     // same for rowA1
    const int rB7 = rowB & 7;

    float acc[4][2][2][4];
#pragma unroll
    for (int g = 0; g < 4; g++)
#pragma unroll
        for (int mi = 0; mi < 2; mi++)
#pragma unroll
            for (int ni = 0; ni < 2; ni++)
#pragma unroll
                for (int q = 0; q < 4; q++) acc[g][mi][ni][q] = 0.0f;

    // prologue: chunks 0,1,2
    fill_stage(base + 0 * STAGE_SZ, m0, n0, 0, tid);   CPA_COMMIT();
    fill_stage(base + 1 * STAGE_SZ, m0, n0, 64, tid);  CPA_COMMIT();
    fill_stage(base + 2 * STAGE_SZ, m0, n0, 128, tid); CPA_COMMIT();

    const int NCH = KTOT / 64;  // 64
#pragma unroll 1
    for (int c = 0; c < NCH; c++) {
        if (c + 3 < NCH)
            fill_stage(base + ((c + 3) & 3) * STAGE_SZ, m0, n0, (c + 3) * 64, tid);
        CPA_COMMIT();
        CPA_WAIT3();
        __syncthreads();

        const uint32_t sb = base + (c & 3) * STAGE_SZ;
        const uint32_t Ab = sb + A_OFF, Wb = sb + WP_OFF;

        uint32_t afrag[2][8], bfrag[2][4];

        // prime: A(ks=0), B(ks=0, g=0)
        {
            int u = chA;
            ldsm4(&afrag[0][0], Ab + rowA0 * 128 + ((u ^ rA7) << 4));
            ldsm4(&afrag[0][4], Ab + rowA1 * 128 + ((u ^ rA7) << 4));
            int ub = chB;
            ldsm4(&bfrag[0][0], Wb + rowB * 128 + ((ub ^ rB7) << 4));
        }

#pragma unroll
        for (int ks = 0; ks < 4; ks++) {
            const int ap = ks & 1;
#pragma unroll
            for (int g = 0; g < 4; g++) {
                const int bp = (ks * 4 + g) & 1;
                // prefetch next fragments before issuing MMAs
                if (g < 3) {
                    int row = (g + 1) * 64 + rowB;
                    int ub = ks * 2 + chB;
                    ldsm4(&bfrag[bp ^ 1][0], Wb + row * 128 + ((ub ^ rB7) << 4));
                } else if (ks < 3) {
                    int ua = (ks + 1) * 2 + chA;
                    ldsm4(&afrag[ap ^ 1][0], Ab + rowA0 * 128 + ((ua ^ rA7) << 4));
                    ldsm4(&afrag[ap ^ 1][4], Ab + rowA1 * 128 + ((ua ^ rA7) << 4));
                    int ub = (ks + 1) * 2 + chB;
                    ldsm4(&bfrag[bp ^ 1][0], Wb + rowB * 128 + ((ub ^ rB7) << 4));
                }
                mma16816(acc[g][0][0], &afrag[ap][0], &bfrag[bp][0]);
                mma16816(acc[g][0][1], &afrag[ap][0], &bfrag[bp][2]);
                mma16816(acc[g][1][0], &afrag[ap][4], &bfrag[bp][0]);
                mma16816(acc[g][1][1], &afrag[ap][4], &bfrag[bp][2]);
            }
        }
        __syncthreads();
    }

    // ---- fused LSTM epilogue: acc[g] all live in this thread for same (m,n)
    const int row0 = m0 + warp_m * 32 + (lane >> 2);
    const int col0 = n0 + warp_n * 16 + (lane & 3) * 2;

#pragma unroll
    for (int ni = 0; ni < 2; ni++) {
        const int cc = col0 + ni * 8;
        float2 b_i = *(const float2*)(bi + cc);
        float2 b_f = *(const float2*)(bf + cc);
        float2 b_g = *(const float2*)(bg + cc);
        float2 b_o = *(const float2*)(bo + cc);
#pragma unroll
        for (int mi = 0; mi < 2; mi++) {
#pragma unroll
            for (int half = 0; half < 2; half++) {   // q{0,1} row r, q{2,3} row r+8
                int r = row0 + mi * 16 + half * 8;
                float2 cv = *(const float2*)(c0 + (size_t)r * FFD + cc);
                float out[2];
#pragma unroll
                for (int q = 0; q < 2; q++) {
                    float vi = acc[0][mi][ni][half * 2 + q] + (q ? b_i.y : b_i.x);
                    float vf = acc[1][mi][ni][half * 2 + q] + (q ? b_f.y : b_f.x);
                    float vg = acc[2][mi][ni][half * 2 + q] + (q ? b_g.y : b_g.x);
                    float vo = acc[3][mi][ni][half * 2 + q] + (q ? b_o.y : b_o.x);
                    float ig = 1.0f / (1.0f + expf(-vi));
                    float fg = 1.0f / (1.0f + expf(-vf));
                    float gg = tanhf(vg);
                    float og = 1.0f / (1.0f + expf(-vo));
                    float ccell = fg * (q ? cv.y : cv.x) + ig * gg;
                    out[q] = og * tanhf(ccell);
                }
                *(float2*)(hout + (size_t)r * FFD + cc) = make_float2(out[0], out[1]);
            }
        }
    }
}

// ---------------- kernel_launch ---------------------------------------------
// inputs: behavior, h0, c0, Wi_h, Wi_x, bi, Wf_h, Wf_x, bf, Wg_h, Wg_x, bg,
//         Wo_h, Wo_x, bo
extern "C" void kernel_launch(void* const* d_in, const int* in_sizes, int n_in,
                              void* d_out, int out_size)
{
    const float* behavior = (const float*)d_in[0];
    const float* h0       = (const float*)d_in[1];
    const float* c0       = (const float*)d_in[2];
    const float* Wi_h = (const float*)d_in[3];
    const float* Wi_x = (const float*)d_in[4];
    const float* bi   = (const float*)d_in[5];
    const float* Wf_h = (const float*)d_in[6];
    const float* Wf_x = (const float*)d_in[7];
    const float* bf   = (const float*)d_in[8];
    const float* Wg_h = (const float*)d_in[9];
    const float* Wg_x = (const float*)d_in[10];
    const float* bg   = (const float*)d_in[11];
    const float* Wo_h = (const float*)d_in[12];
    const float* Wo_x = (const float*)d_in[13];
    const float* bo   = (const float*)d_in[14];
    float* hout = (float*)d_out;

    cudaFuncSetAttribute(lstm_gemm_kernel,
                         cudaFuncAttributeMaxDynamicSharedMemorySize, SMEM_TOTAL);

    conv_A_kernel<<<(int)(((size_t)NN * KTOT / 4) / 256), 256>>>(h0, behavior);
    conv_W_kernel<<<dim3(2048 / 32, 2048 / 32, 8), dim3(256)>>>(
        Wi_h, Wi_x, Wf_h, Wf_x, Wg_h, Wg_x, Wo_h, Wo_x);
    lstm_gemm_kernel<<<dim3(FFD / 64, NN / 128), 512, SMEM_TOTAL>>>(
        c0, hout, bi, bf, bg, bo);
}

// round 9
// speedup vs baseline: 1.0039x; 1.0039x over previous
#include <cuda_runtime.h>
#include <cuda_fp16.h>
#include <cstdint>
#include <math.h>

#define NN   4096
#define FFD  2048
#define KTOT 4096   // concat K: [h0 (2048) | behavior (2048)]

// ---------------- device scratch (no cudaMalloc allowed) -------------------
static __device__ __half g_A[(size_t)NN * KTOT];              // 33.5MB  A fp16
static __device__ __half g_W[(size_t)4 * FFD * KTOT];         // 67MB    W^T fp16 [g*FFD+n][k]

// ---------------- helpers ---------------------------------------------------
__device__ __forceinline__ uint32_t smem_u32(const void* p) {
    uint32_t a;
    asm("{ .reg .u64 t; cvta.to.shared.u64 t, %1; cvt.u32.u64 %0, t; }"
        : "=r"(a) : "l"(p));
    return a;
}
__device__ __forceinline__ void cpa16(uint32_t s, const void* g) {
    asm volatile("cp.async.cg.shared.global [%0], [%1], 16;" :: "r"(s), "l"(g));
}
#define CPA_COMMIT() asm volatile("cp.async.commit_group;" ::: "memory")
#define CPA_WAIT3()  asm volatile("cp.async.wait_group 3;" ::: "memory")

__device__ __forceinline__ void ldsm4(uint32_t* r, uint32_t addr) {
    asm volatile("ldmatrix.sync.aligned.m8n8.x4.shared.b16 {%0,%1,%2,%3}, [%4];"
                 : "=r"(r[0]), "=r"(r[1]), "=r"(r[2]), "=r"(r[3]) : "r"(addr));
}
__device__ __forceinline__ void mma16816(float* c, const uint32_t* a, const uint32_t* b) {
    asm volatile("mma.sync.aligned.m16n8k16.row.col.f32.f16.f16.f32 "
                 "{%0,%1,%2,%3}, {%4,%5,%6,%7}, {%8,%9}, {%0,%1,%2,%3};"
                 : "+f"(c[0]), "+f"(c[1]), "+f"(c[2]), "+f"(c[3])
                 : "r"(a[0]), "r"(a[1]), "r"(a[2]), "r"(a[3]),
                   "r"(b[0]), "r"(b[1]));
}

// ---------------- merged pre-pass: A convert + W transpose/convert ----------
// blocks [0, 4096):        A = [h0 | behavior] -> fp16, 4 float4 per thread
// blocks [4096, 36864):    W transpose+convert, one 32x32 tile per block
__global__ __launch_bounds__(256)
void conv_AW_kernel(const float* __restrict__ h0, const float* __restrict__ beh,
                    const float* Wi_h, const float* Wi_x,
                    const float* Wf_h, const float* Wf_x,
                    const float* Wg_h, const float* Wg_x,
                    const float* Wo_h, const float* Wo_x)
{
    const int b = blockIdx.x;
    const int tid = threadIdx.x;

    if (b < 4096) {
        // ---- A conversion: 4 independent float4s per thread (MLP=4) ----
#pragma unroll
        for (int i = 0; i < 4; i++) {
            size_t e = ((size_t)b * 1024 + i * 256 + tid) * 4;
            int m = (int)(e >> 12);
            int k = (int)(e & 4095);
            const float* src = (k < 2048) ? (h0 + (size_t)m * 2048 + k)
                                          : (beh + (size_t)m * 2048 + (k - 2048));
            float4 v = *(const float4*)src;
            __half2* dh = (__half2*)(g_A + e);
            dh[0] = __halves2half2(__float2half_rn(v.x), __float2half_rn(v.y));
            dh[1] = __halves2half2(__float2half_rn(v.z), __float2half_rn(v.w));
        }
        return;
    }

    // ---- W transpose: src [K=2048][N=2048] fp32 -> g_W[(g*FFD+n)*KTOT + isx*2048 + k]
    const float* srcs[8] = {Wi_h, Wi_x, Wf_h, Wf_x, Wg_h, Wg_x, Wo_h, Wo_x};
    const int bb = b - 4096;
    const int z = bb >> 12;           // 0..7: matrix index
    const int t = bb & 4095;          // 64x64 tiles of 32x32
    const int g = z >> 1, isx = z & 1;
    const float* __restrict__ src = srcs[z];
    const int k0 = (t >> 6) * 32, n0 = (t & 63) * 32;

    __shared__ __half tt[32][33];     // [k_local][n_local], padded

    {   // phase 1: coalesced fp32 reads (n contiguous), convert, half to smem
        int n_l = tid & 31;
        int k_l = tid >> 5;           // 0..7
#pragma unroll
        for (int i = 0; i < 4; i++) {
            int kk = k_l + i * 8;
            tt[kk][n_l] = __float2half_rn(src[(size_t)(k0 + kk) * 2048 + n0 + n_l]);
        }
    }
    __syncthreads();

    {   // phase 2: pack 4 consecutive k for one n -> 8B store
        int n_l = tid >> 3;           // 0..31
        int k_q = (tid & 7) * 4;      // 0,4,...,28
        __half2 p0 = __halves2half2(tt[k_q + 0][n_l], tt[k_q + 1][n_l]);
        __half2 p1 = __halves2half2(tt[k_q + 2][n_l], tt[k_q + 3][n_l]);
        size_t o = ((size_t)g * FFD + n0 + n_l) * KTOT + isx * 2048 + k0 + k_q;
        __half2* dst = (__half2*)(g_W + o);
        dst[0] = p0;
        dst[1] = p1;
    }
}

// ---------------- fused 4-gate GEMM + LSTM epilogue -------------------------
// BM=128, BN=64 per gate (x4 gates), BK=64, 4 stages, 512 threads.
// 16 warps: warp_m in {0..3} (32 rows), warp_n in {0..3} (16 cols).
static constexpr int A_OFF    = 0;        // 128 rows x 128B = 16KB
static constexpr int WP_OFF   = 16384;    // 4 gates x 64 rows x 128B = 32KB
static constexpr int STAGE_SZ = 49152;    // 48KB
static constexpr int SMEM_TOTAL = 4 * STAGE_SZ;  // 192KB

__device__ __forceinline__ void fill_stage(uint32_t sb, int m0, int n0, int kb, int tid) {
#pragma unroll
    for (int i = 0; i < 2; i++) {               // A: 1024 16B units
        int u = tid + i * 512;
        int row = u >> 3, cu = u & 7;
        uint32_t sw = (uint32_t)(row * 128 + ((cu ^ (row & 7)) << 4));
        size_t go = (size_t)(m0 + row) * KTOT + kb + cu * 8;
        cpa16(sb + A_OFF + sw, g_A + go);
    }
#pragma unroll
    for (int i = 0; i < 4; i++) {               // W: 2048 16B units (4 gates x 64 rows)
        int u = tid + i * 512;
        int row = u >> 3, cu = u & 7;           // row 0..255: gate = row>>6, n = row&63
        uint32_t sw = (uint32_t)(row * 128 + ((cu ^ (row & 7)) << 4));
        size_t go = ((size_t)(row >> 6) * FFD + n0 + (row & 63)) * KTOT + kb + cu * 8;
        cpa16(sb + WP_OFF + sw, g_W + go);
    }
}

__global__ __launch_bounds__(512, 1)
void lstm_gemm_kernel(const float* __restrict__ c0, float* __restrict__ hout,
                      const float* __restrict__ bi, const float* __restrict__ bf,
                      const float* __restrict__ bg, const float* __restrict__ bo)
{
    extern __shared__ __align__(1024) char smem[];
    const uint32_t base = smem_u32(smem);
    const int tid = threadIdx.x;
    const int wid = tid >> 5;
    const int lane = tid & 31;
    const int warp_m = wid & 3;    // 4 warps over M (32 rows each)
    const int warp_n = wid >> 2;   // 4 warps over N (16 cols each)
    const int m0 = blockIdx.y * 128;
    const int n0 = blockIdx.x * 64;

    const int quad = lane >> 3, rr = lane & 7;
    const int rowA0 = warp_m * 32 + (quad & 1) * 8 + rr;      // + mi*16
    const int rowA1 = rowA0 + 16;
    const int chA = quad >> 1;
    const int rowB  = warp_n * 16 + (quad >> 1) * 8 + rr;     // within 64-row gate slab
    const int chB = quad & 1;
    const int rA7 = rowA0 & 7;     // same for rowA1
    const int rB7 = rowB & 7;

    float acc[4][2][2][4];
#pragma unroll
    for (int g = 0; g < 4; g++)
#pragma unroll
        for (int mi = 0; mi < 2; mi++)
#pragma unroll
            for (int ni = 0; ni < 2; ni++)
#pragma unroll
                for (int q = 0; q < 4; q++) acc[g][mi][ni][q] = 0.0f;

    // prologue: chunks 0,1,2
    fill_stage(base + 0 * STAGE_SZ, m0, n0, 0, tid);   CPA_COMMIT();
    fill_stage(base + 1 * STAGE_SZ, m0, n0, 64, tid);  CPA_COMMIT();
    fill_stage(base + 2 * STAGE_SZ, m0, n0, 128, tid); CPA_COMMIT();

    const int NCH = KTOT / 64;  // 64
#pragma unroll 1
    for (int c = 0; c < NCH; c++) {
        if (c + 3 < NCH)
            fill_stage(base + ((c + 3) & 3) * STAGE_SZ, m0, n0, (c + 3) * 64, tid);
        CPA_COMMIT();
        CPA_WAIT3();
        __syncthreads();

        const uint32_t sb = base + (c & 3) * STAGE_SZ;
        const uint32_t Ab = sb + A_OFF, Wb = sb + WP_OFF;

        uint32_t afrag[2][8], bfrag[2][4];

        // prime: A(ks=0), B(ks=0, g=0)
        {
            int u = chA;
            ldsm4(&afrag[0][0], Ab + rowA0 * 128 + ((u ^ rA7) << 4));
            ldsm4(&afrag[0][4], Ab + rowA1 * 128 + ((u ^ rA7) << 4));
            int ub = chB;
            ldsm4(&bfrag[0][0], Wb + rowB * 128 + ((ub ^ rB7) << 4));
        }

#pragma unroll
        for (int ks = 0; ks < 4; ks++) {
            const int ap = ks & 1;
#pragma unroll
            for (int g = 0; g < 4; g++) {
                const int bp = (ks * 4 + g) & 1;
                // prefetch next fragments before issuing MMAs
                if (g < 3) {
                    int row = (g + 1) * 64 + rowB;
                    int ub = ks * 2 + chB;
                    ldsm4(&bfrag[bp ^ 1][0], Wb + row * 128 + ((ub ^ rB7) << 4));
                } else if (ks < 3) {
                    int ua = (ks + 1) * 2 + chA;
                    ldsm4(&afrag[ap ^ 1][0], Ab + rowA0 * 128 + ((ua ^ rA7) << 4));
                    ldsm4(&afrag[ap ^ 1][4], Ab + rowA1 * 128 + ((ua ^ rA7) << 4));
                    int ub = (ks + 1) * 2 + chB;
                    ldsm4(&bfrag[bp ^ 1][0], Wb + rowB * 128 + ((ub ^ rB7) << 4));
                }
                mma16816(acc[g][0][0], &afrag[ap][0], &bfrag[bp][0]);
                mma16816(acc[g][0][1], &afrag[ap][0], &bfrag[bp][2]);
                mma16816(acc[g][1][0], &afrag[ap][4], &bfrag[bp][0]);
                mma16816(acc[g][1][1], &afrag[ap][4], &bfrag[bp][2]);
            }
        }
        __syncthreads();
    }

    // ---- fused LSTM epilogue: acc[g] all live in this thread for same (m,n)
    const int row0 = m0 + warp_m * 32 + (lane >> 2);
    const int col0 = n0 + warp_n * 16 + (lane & 3) * 2;

#pragma unroll
    for (int ni = 0; ni < 2; ni++) {
        const int cc = col0 + ni * 8;
        float2 b_i = *(const float2*)(bi + cc);
        float2 b_f = *(const float2*)(bf + cc);
        float2 b_g = *(const float2*)(bg + cc);
        float2 b_o = *(const float2*)(bo + cc);
#pragma unroll
        for (int mi = 0; mi < 2; mi++) {
#pragma unroll
            for (int half = 0; half < 2; half++) {   // q{0,1} row r, q{2,3} row r+8
                int r = row0 + mi * 16 + half * 8;
                float2 cv = *(const float2*)(c0 + (size_t)r * FFD + cc);
                float out[2];
#pragma unroll
                for (int q = 0; q < 2; q++) {
                    float vi = acc[0][mi][ni][half * 2 + q] + (q ? b_i.y : b_i.x);
                    float vf = acc[1][mi][ni][half * 2 + q] + (q ? b_f.y : b_f.x);
                    float vg = acc[2][mi][ni][half * 2 + q] + (q ? b_g.y : b_g.x);
                    float vo = acc[3][mi][ni][half * 2 + q] + (q ? b_o.y : b_o.x);
                    float ig = 1.0f / (1.0f + expf(-vi));
                    float fg = 1.0f / (1.0f + expf(-vf));
                    float gg = tanhf(vg);
                    float og = 1.0f / (1.0f + expf(-vo));
                    float ccell = fg * (q ? cv.y : cv.x) + ig * gg;
                    out[q] = og * tanhf(ccell);
                }
                *(float2*)(hout + (size_t)r * FFD + cc) = make_float2(out[0], out[1]);
            }
        }
    }
}

// ---------------- kernel_launch ---------------------------------------------
// inputs: behavior, h0, c0, Wi_h, Wi_x, bi, Wf_h, Wf_x, bf, Wg_h, Wg_x, bg,
//         Wo_h, Wo_x, bo
extern "C" void kernel_launch(void* const* d_in, const int* in_sizes, int n_in,
                              void* d_out, int out_size)
{
    const float* behavior = (const float*)d_in[0];
    const float* h0       = (const float*)d_in[1];
    const float* c0       = (const float*)d_in[2];
    const float* Wi_h = (const float*)d_in[3];
    const float* Wi_x = (const float*)d_in[4];
    const float* bi   = (const float*)d_in[5];
    const float* Wf_h = (const float*)d_in[6];
    const float* Wf_x = (const float*)d_in[7];
    const float* bf   = (const float*)d_in[8];
    const float* Wg_h = (const float*)d_in[9];
    const float* Wg_x = (const float*)d_in[10];
    const float* bg   = (const float*)d_in[11];
    const float* Wo_h = (const float*)d_in[12];
    const float* Wo_x = (const float*)d_in[13];
    const float* bo   = (const float*)d_in[14];
    float* hout = (float*)d_out;

    cudaFuncSetAttribute(lstm_gemm_kernel,
                         cudaFuncAttributeMaxDynamicSharedMemorySize, SMEM_TOTAL);

    // merged pre-pass: 4096 A-blocks + 32768 W-blocks, concurrent
    conv_AW_kernel<<<36864, 256>>>(h0, behavior,
                                   Wi_h, Wi_x, Wf_h, Wf_x,
                                   Wg_h, Wg_x, Wo_h, Wo_x);
    lstm_gemm_kernel<<<dim3(FFD / 64, NN / 128), 512, SMEM_TOTAL>>>(
        c0, hout, bi, bf, bg, bo);
}

// round 10
// speedup vs baseline: 1.1048x; 1.1006x over previous
#include <cuda_runtime.h>
#include <cuda_fp16.h>
#include <cstdint>
#include <math.h>

#define NN   4096
#define FFD  2048
#define KTOT 4096   // concat K: [h0 (2048) | behavior (2048)]

// ---------------- device scratch (no cudaMalloc allowed) -------------------
static __device__ __half g_A[(size_t)NN * KTOT];              // 33.5MB  A fp16
static __device__ __half g_W[(size_t)4 * FFD * KTOT];         // 67MB    W^T fp16 [g*FFD+n][k]

// ---------------- helpers ---------------------------------------------------
__device__ __forceinline__ uint32_t smem_u32(const void* p) {
    uint32_t a;
    asm("{ .reg .u64 t; cvta.to.shared.u64 t, %1; cvt.u32.u64 %0, t; }"
        : "=r"(a) : "l"(p));
    return a;
}
__device__ __forceinline__ void cpa16(uint32_t s, const void* g) {
    asm volatile("cp.async.cg.shared.global [%0], [%1], 16;" :: "r"(s), "l"(g));
}
#define CPA_COMMIT() asm volatile("cp.async.commit_group;" ::: "memory")
#define CPA_WAIT2()  asm volatile("cp.async.wait_group 2;" ::: "memory")

__device__ __forceinline__ void ldsm4(uint32_t* r, uint32_t addr) {
    asm volatile("ldmatrix.sync.aligned.m8n8.x4.shared.b16 {%0,%1,%2,%3}, [%4];"
                 : "=r"(r[0]), "=r"(r[1]), "=r"(r[2]), "=r"(r[3]) : "r"(addr));
}
__device__ __forceinline__ void mma16816(float* c, const uint32_t* a, const uint32_t* b) {
    asm volatile("mma.sync.aligned.m16n8k16.row.col.f32.f16.f16.f32 "
                 "{%0,%1,%2,%3}, {%4,%5,%6,%7}, {%8,%9}, {%0,%1,%2,%3};"
                 : "+f"(c[0]), "+f"(c[1]), "+f"(c[2]), "+f"(c[3])
                 : "r"(a[0]), "r"(a[1]), "r"(a[2]), "r"(a[3]),
                   "r"(b[0]), "r"(b[1]));
}

// ---------------- merged pre-pass: A convert + W transpose/convert ----------
__global__ __launch_bounds__(256)
void conv_AW_kernel(const float* __restrict__ h0, const float* __restrict__ beh,
                    const float* Wi_h, const float* Wi_x,
                    const float* Wf_h, const float* Wf_x,
                    const float* Wg_h, const float* Wg_x,
                    const float* Wo_h, const float* Wo_x)
{
    const int b = blockIdx.x;
    const int tid = threadIdx.x;

    if (b < 4096) {
        // ---- A conversion: 4 independent float4s per thread (MLP=4) ----
#pragma unroll
        for (int i = 0; i < 4; i++) {
            size_t e = ((size_t)b * 1024 + i * 256 + tid) * 4;
            int m = (int)(e >> 12);
            int k = (int)(e & 4095);
            const float* src = (k < 2048) ? (h0 + (size_t)m * 2048 + k)
                                          : (beh + (size_t)m * 2048 + (k - 2048));
            float4 v = *(const float4*)src;
            __half2* dh = (__half2*)(g_A + e);
            dh[0] = __halves2half2(__float2half_rn(v.x), __float2half_rn(v.y));
            dh[1] = __halves2half2(__float2half_rn(v.z), __float2half_rn(v.w));
        }
        return;
    }

    // ---- W transpose: src [K=2048][N=2048] fp32 -> g_W[(g*FFD+n)*KTOT + isx*2048 + k]
    const float* srcs[8] = {Wi_h, Wi_x, Wf_h, Wf_x, Wg_h, Wg_x, Wo_h, Wo_x};
    const int bb = b - 4096;
    const int z = bb >> 12;           // 0..7: matrix index
    const int t = bb & 4095;          // 64x64 tiles of 32x32
    const int g = z >> 1, isx = z & 1;
    const float* __restrict__ src = srcs[z];
    const int k0 = (t >> 6) * 32, n0 = (t & 63) * 32;

    __shared__ __half tt[32][33];     // [k_local][n_local], padded

    {   // phase 1: coalesced fp32 reads, convert, half to smem
        int n_l = tid & 31;
        int k_l = tid >> 5;           // 0..7
#pragma unroll
        for (int i = 0; i < 4; i++) {
            int kk = k_l + i * 8;
            tt[kk][n_l] = __float2half_rn(src[(size_t)(k0 + kk) * 2048 + n0 + n_l]);
        }
    }
    __syncthreads();

    {   // phase 2: pack 4 consecutive k for one n -> 8B store
        int n_l = tid >> 3;           // 0..31
        int k_q = (tid & 7) * 4;      // 0,4,...,28
        __half2 p0 = __halves2half2(tt[k_q + 0][n_l], tt[k_q + 1][n_l]);
        __half2 p1 = __halves2half2(tt[k_q + 2][n_l], tt[k_q + 3][n_l]);
        size_t o = ((size_t)g * FFD + n0 + n_l) * KTOT + isx * 2048 + k0 + k_q;
        __half2* dst = (__half2*)(g_W + o);
        dst[0] = p0;
        dst[1] = p1;
    }
}

// ---------------- fused 4-gate GEMM + LSTM epilogue -------------------------
// BM=128, BN=32 per gate (x4 gates), BK=64, 3 stages, 256 threads, 2 CTAs/SM.
// 8 warps: warp_m in {0..3} (32 rows), warp_n in {0..1} (16 cols per gate).
static constexpr int A_OFF    = 0;        // 128 rows x 128B = 16KB
static constexpr int WP_OFF   = 16384;    // 4 gates x 32 rows x 128B = 16KB
static constexpr int STAGE_SZ = 32768;    // 32KB
static constexpr int SMEM_TOTAL = 3 * STAGE_SZ;  // 96KB -> 2 CTAs/SM

__device__ __forceinline__ void fill_stage(uint32_t sb, int m0, int n0, int kb, int tid) {
#pragma unroll
    for (int i = 0; i < 4; i++) {               // A: 1024 16B units
        int u = tid + i * 256;
        int row = u >> 3, cu = u & 7;
        uint32_t sw = (uint32_t)(row * 128 + ((cu ^ (row & 7)) << 4));
        size_t go = (size_t)(m0 + row) * KTOT + kb + cu * 8;
        cpa16(sb + A_OFF + sw, g_A + go);
    }
#pragma unroll
    for (int i = 0; i < 4; i++) {               // W: 1024 16B units (4 gates x 32 rows)
        int u = tid + i * 256;
        int row = u >> 3, cu = u & 7;           // row 0..127: gate = row>>5, n = row&31
        uint32_t sw = (uint32_t)(row * 128 + ((cu ^ (row & 7)) << 4));
        size_t go = ((size_t)(row >> 5) * FFD + n0 + (row & 31)) * KTOT + kb + cu * 8;
        cpa16(sb + WP_OFF + sw, g_W + go);
    }
}

__global__ __launch_bounds__(256, 2)
void lstm_gemm_kernel(const float* __restrict__ c0, float* __restrict__ hout,
                      const float* __restrict__ bi, const float* __restrict__ bf,
                      const float* __restrict__ bg, const float* __restrict__ bo)
{
    extern __shared__ __align__(1024) char smem[];
    const uint32_t base = smem_u32(smem);
    const int tid = threadIdx.x;
    const int wid = tid >> 5;
    const int lane = tid & 31;
    const int warp_m = wid & 3;    // 4 warps over M (32 rows each)
    const int warp_n = wid >> 2;   // 2 warps over N (16 cols per gate each)
    const int m0 = blockIdx.y * 128;
    const int n0 = blockIdx.x * 32;

    const int quad = lane >> 3, rr = lane & 7;
    const int rowA0 = warp_m * 32 + (quad & 1) * 8 + rr;      // + mi*16
    const int rowA1 = rowA0 + 16;
    const int chA = quad >> 1;
    const int rowB  = warp_n * 16 + (quad >> 1) * 8 + rr;     // within 32-row gate slab
    const int chB = quad & 1;
    const int rA7 = rowA0 & 7;
    const int rB7 = rowB & 7;

    float acc[4][2][2][4];
#pragma unroll
    for (int g = 0; g < 4; g++)
#pragma unroll
        for (int mi = 0; mi < 2; mi++)
#pragma unroll
            for (int ni = 0; ni < 2; ni++)
#pragma unroll
                for (int q = 0; q < 4; q++) acc[g][mi][ni][q] = 0.0f;

    // prologue: chunks 0,1
    fill_stage(base + 0 * STAGE_SZ, m0, n0, 0, tid);   CPA_COMMIT();
    fill_stage(base + 1 * STAGE_SZ, m0, n0, 64, tid);  CPA_COMMIT();

    const int NCH = KTOT / 64;  // 64
    int sidx = 0;               // stage index of chunk c (mod 3)
#pragma unroll 1
    for (int c = 0; c < NCH; c++) {
        if (c + 2 < NCH) {
            int ps = sidx + 2; if (ps >= 3) ps -= 3;
            fill_stage(base + ps * STAGE_SZ, m0, n0, (c + 2) * 64, tid);
        }
        CPA_COMMIT();
        CPA_WAIT2();
        __syncthreads();

        const uint32_t sb = base + sidx * STAGE_SZ;
        const uint32_t Ab = sb + A_OFF, Wb = sb + WP_OFF;

        uint32_t afrag[2][8], bfrag[2][4];

        // prime: A(ks=0), B(ks=0, g=0)
        {
            int u = chA;
            ldsm4(&afrag[0][0], Ab + rowA0 * 128 + ((u ^ rA7) << 4));
            ldsm4(&afrag[0][4], Ab + rowA1 * 128 + ((u ^ rA7) << 4));
            int ub = chB;
            ldsm4(&bfrag[0][0], Wb + rowB * 128 + ((ub ^ rB7) << 4));
        }

#pragma unroll
        for (int ks = 0; ks < 4; ks++) {
            const int ap = ks & 1;
#pragma unroll
            for (int g = 0; g < 4; g++) {
                const int bp = (ks * 4 + g) & 1;
                // prefetch next fragments before issuing MMAs
                if (g < 3) {
                    int row = (g + 1) * 32 + rowB;
                    int ub = ks * 2 + chB;
                    ldsm4(&bfrag[bp ^ 1][0], Wb + row * 128 + ((ub ^ rB7) << 4));
                } else if (ks < 3) {
                    int ua = (ks + 1) * 2 + chA;
                    ldsm4(&afrag[ap ^ 1][0], Ab + rowA0 * 128 + ((ua ^ rA7) << 4));
                    ldsm4(&afrag[ap ^ 1][4], Ab + rowA1 * 128 + ((ua ^ rA7) << 4));
                    int ub = (ks + 1) * 2 + chB;
                    ldsm4(&bfrag[bp ^ 1][0], Wb + rowB * 128 + ((ub ^ rB7) << 4));
                }
                mma16816(acc[g][0][0], &afrag[ap][0], &bfrag[bp][0]);
                mma16816(acc[g][0][1], &afrag[ap][0], &bfrag[bp][2]);
                mma16816(acc[g][1][0], &afrag[ap][4], &bfrag[bp][0]);
                mma16816(acc[g][1][1], &afrag[ap][4], &bfrag[bp][2]);
            }
        }
        __syncthreads();
        if (++sidx >= 3) sidx = 0;
    }

    // ---- fused LSTM epilogue: acc[g] all live in this thread for same (m,n)
    const int row0 = m0 + warp_m * 32 + (lane >> 2);
    const int col0 = n0 + warp_n * 16 + (lane & 3) * 2;

#pragma unroll
    for (int ni = 0; ni < 2; ni++) {
        const int cc = col0 + ni * 8;
        float2 b_i = *(const float2*)(bi + cc);
        float2 b_f = *(const float2*)(bf + cc);
        float2 b_g = *(const float2*)(bg + cc);
        float2 b_o = *(const float2*)(bo + cc);
#pragma unroll
        for (int mi = 0; mi < 2; mi++) {
#pragma unroll
            for (int half = 0; half < 2; half++) {   // q{0,1} row r, q{2,3} row r+8
                int r = row0 + mi * 16 + half * 8;
                float2 cv = *(const float2*)(c0 + (size_t)r * FFD + cc);
                float out[2];
#pragma unroll
                for (int q = 0; q < 2; q++) {
                    float vi = acc[0][mi][ni][half * 2 + q] + (q ? b_i.y : b_i.x);
                    float vf = acc[1][mi][ni][half * 2 + q] + (q ? b_f.y : b_f.x);
                    float vg = acc[2][mi][ni][half * 2 + q] + (q ? b_g.y : b_g.x);
                    float vo = acc[3][mi][ni][half * 2 + q] + (q ? b_o.y : b_o.x);
                    float ig = 1.0f / (1.0f + expf(-vi));
                    float fg = 1.0f / (1.0f + expf(-vf));
                    float gg = tanhf(vg);
                    float og = 1.0f / (1.0f + expf(-vo));
                    float ccell = fg * (q ? cv.y : cv.x) + ig * gg;
                    out[q] = og * tanhf(ccell);
                }
                *(float2*)(hout + (size_t)r * FFD + cc) = make_float2(out[0], out[1]);
            }
        }
    }
}

// ---------------- kernel_launch ---------------------------------------------
// inputs: behavior, h0, c0, Wi_h, Wi_x, bi, Wf_h, Wf_x, bf, Wg_h, Wg_x, bg,
//         Wo_h, Wo_x, bo
extern "C" void kernel_launch(void* const* d_in, const int* in_sizes, int n_in,
                              void* d_out, int out_size)
{
    const float* behavior = (const float*)d_in[0];
    const float* h0       = (const float*)d_in[1];
    const float* c0       = (const float*)d_in[2];
    const float* Wi_h = (const float*)d_in[3];
    const float* Wi_x = (const float*)d_in[4];
    const float* bi   = (const float*)d_in[5];
    const float* Wf_h = (const float*)d_in[6];
    const float* Wf_x = (const float*)d_in[7];
    const float* bf   = (const float*)d_in[8];
    const float* Wg_h = (const float*)d_in[9];
    const float* Wg_x = (const float*)d_in[10];
    const float* bg   = (const float*)d_in[11];
    const float* Wo_h = (const float*)d_in[12];
    const float* Wo_x = (const float*)d_in[13];
    const float* bo   = (const float*)d_in[14];
    float* hout = (float*)d_out;

    cudaFuncSetAttribute(lstm_gemm_kernel,
                         cudaFuncAttributeMaxDynamicSharedMemorySize, SMEM_TOTAL);

    conv_AW_kernel<<<36864, 256>>>(h0, behavior,
                                   Wi_h, Wi_x, Wf_h, Wf_x,
                                   Wg_h, Wg_x, Wo_h, Wo_x);
    lstm_gemm_kernel<<<dim3(FFD / 32, NN / 128), 256, SMEM_TOTAL>>>(
        c0, hout, bi, bf, bg, bo);
}